// round 6
// baseline (speedup 1.0000x reference)
#include <cuda_runtime.h>
#include <math.h>

#define H        2048
#define E        8
#define TPB      128                 // tokens per block
#define NTHR     512                 // 16 warps: 4 token-groups x 4 H-quarters
#define NQ       4                   // H quarters
#define HQ       (H / NQ)            // 512
#define SG       16                  // floats per stage per quarter per token
#define NSTG     (HQ / SG)           // 32 stages
#define NBUF     4
#define TOK_STRIDE 272               // bytes/token/stage: 4*64B data + 16B pad
#define XBUF_BYTES (TPB * TOK_STRIDE)     // 34816
#define W_BYTES  (E * H * 4)         // 65536
#define ALPHA    0.01f

__device__ float        g_acc[2 * E];   // [0..7] counts, [8..15] prob sums
__device__ unsigned int g_done = 0;

__device__ __forceinline__ void ffma2(unsigned long long& d,
                                      unsigned long long a,
                                      unsigned long long b)
{
    asm("fma.rn.f32x2 %0, %1, %2, %0;" : "+l"(d) : "l"(a), "l"(b));
}

__device__ __forceinline__ float pair_sum(unsigned long long p)
{
    float lo, hi;
    asm("mov.b64 {%0, %1}, %2;" : "=f"(lo), "=f"(hi) : "l"(p));
    return lo + hi;
}

__device__ __forceinline__ void cp16(unsigned int saddr, const void* gaddr)
{
    asm volatile("cp.async.cg.shared.global [%0], [%1], 16;"
                 :: "r"(saddr), "l"(gaddr));
}

__global__ __launch_bounds__(NTHR, 1)
void moe_gate_kernel(const float* __restrict__ x,
                     const float* __restrict__ w,
                     float* __restrict__ out_idx,
                     float* __restrict__ out_wgt,
                     float* __restrict__ out_aux,
                     int T)
{
    extern __shared__ char smem[];
    float* wsm = reinterpret_cast<float*>(smem);          // 64KB weights
    char*  xb  = smem + W_BYTES;                          // 4 x-buffers
    const unsigned int smem_u32 =
        (unsigned int)__cvta_generic_to_shared(smem);
    const unsigned int xb_u32 = smem_u32 + W_BYTES;

    __shared__ float s_cnt[E];
    __shared__ float s_psum[E];
    __shared__ unsigned int s_last;

    const int tid  = threadIdx.x;
    const int warp = tid >> 5;
    const int lane = tid & 31;
    const int tg   = warp >> 2;      // token group 0..3
    const int q    = warp & 3;       // H quarter 0..3
    const int tok0 = blockIdx.x * TPB;

    if (tid < E)            s_cnt[tid] = 0.0f;
    else if (tid < 2 * E)   s_psum[tid - E] = 0.0f;

    // ---- cp.async stage issuer: stage s covers h = q*HQ + s*SG .. +SG ----
    auto issue_stage = [&](int s, int buf) {
        const unsigned int sb = xb_u32 + buf * XBUF_BYTES;
        #pragma unroll
        for (int k = 0; k < 4; k++) {
            const int o   = tid + k * NTHR;     // 0..2047
            const int tok = o >> 4;
            const int rem = o & 15;
            const int qq  = rem >> 2;
            const int p   = rem & 3;
            const float* g = x + (size_t)(tok0 + tok) * H
                           + qq * HQ + s * SG + p * 4;
            cp16(sb + tok * TOK_STRIDE + qq * 64 + p * 16, g);
        }
        asm volatile("cp.async.commit_group;");
    };

    // prologue: stages 0 and 1 in flight, then stage weights
    issue_stage(0, 0);
    issue_stage(1, 1);
    {
        float4*       ws = reinterpret_cast<float4*>(wsm);
        const float4* wg = reinterpret_cast<const float4*>(w);
        #pragma unroll
        for (int i = 0; i < (E * H / 4) / NTHR; i++)
            ws[tid + i * NTHR] = wg[tid + i * NTHR];
    }

    unsigned long long acc2[E];      // packed h-pair sums for this quarter
    #pragma unroll
    for (int e = 0; e < E; e++) acc2[e] = 0ull;

    const char*  xlane_base = xb + (tg * 32 + lane) * TOK_STRIDE + q * 64;
    const float* wq         = wsm + q * HQ;

    for (int it = 0; it < NSTG; it++) {
        if (it + 2 < NSTG) issue_stage(it + 2, (it + 2) & 3);
        else               asm volatile("cp.async.commit_group;");
        asm volatile("cp.async.wait_group 2;");
        __syncthreads();

        const char* xp = xlane_base + (it & 3) * XBUF_BYTES;
        ulonglong2 xv[4];
        #pragma unroll
        for (int j = 0; j < 4; j++)
            xv[j] = *reinterpret_cast<const ulonglong2*>(xp + j * 16);

        const float* wst = wq + it * SG;
        #pragma unroll
        for (int e = 0; e < E; e++) {
            const ulonglong2* wrow =
                reinterpret_cast<const ulonglong2*>(wst + e * H);
            #pragma unroll
            for (int j = 0; j < 4; j++) {
                const ulonglong2 wv = wrow[j];      // broadcast LDS.128
                ffma2(acc2[e], xv[j].x, wv.x);
                ffma2(acc2[e], xv[j].y, wv.y);
            }
        }
    }

    // ---- publish quarter-partials (alias x buffer 0; stage reads done) ----
    float* sp = reinterpret_cast<float*>(xb);   // [NQ][TPB][9]
    {
        const int tok = tg * 32 + lane;
        float* row = sp + ((size_t)q * TPB + tok) * 9;
        #pragma unroll
        for (int e = 0; e < E; e++) row[e] = pair_sum(acc2[e]);
    }
    __syncthreads();

    // ---- one thread per token: combine quarters, softmax, top-2 ----
    if (tid < TPB) {
        const int tok = tok0 + tid;
        float lg[E];
        #pragma unroll
        for (int e = 0; e < E; e++) {
            float v = 0.0f;
            #pragma unroll
            for (int qq = 0; qq < NQ; qq++)
                v += sp[((size_t)qq * TPB + tid) * 9 + e];
            lg[e] = v;
        }

        float m = lg[0];
        #pragma unroll
        for (int e = 1; e < E; e++) m = fmaxf(m, lg[e]);
        float p[E];
        float s = 0.0f;
        #pragma unroll
        for (int e = 0; e < E; e++) { p[e] = __expf(lg[e] - m); s += p[e]; }
        const float inv = 1.0f / s;

        int i1 = 0; float b1 = lg[0];
        #pragma unroll
        for (int e = 1; e < E; e++)
            if (lg[e] > b1) { b1 = lg[e]; i1 = e; }
        int i2 = -1; float b2 = -INFINITY;
        #pragma unroll
        for (int e = 0; e < E; e++)
            if (e != i1 && lg[e] > b2) { b2 = lg[e]; i2 = e; }

        out_idx[2 * tok]     = (float)i1;
        out_idx[2 * tok + 1] = (float)i2;
        out_wgt[2 * tok]     = p[i1] * inv;
        out_wgt[2 * tok + 1] = p[i2] * inv;

        atomicAdd(&s_cnt[i1], 1.0f);
        atomicAdd(&s_cnt[i2], 1.0f);
        #pragma unroll
        for (int e = 0; e < E; e++)
            atomicAdd(&s_psum[e], p[e] * inv);
    }

    __syncthreads();
    if (tid < E)           atomicAdd(&g_acc[tid], s_cnt[tid]);
    else if (tid < 2 * E)  atomicAdd(&g_acc[tid], s_psum[tid - E]);
    __threadfence();
    __syncthreads();

    if (tid == 0)
        s_last = (atomicAdd(&g_done, 1u) == gridDim.x - 1) ? 1u : 0u;
    __syncthreads();

    if (s_last && tid == 0) {
        float aux = 0.0f;
        const float invT  = 1.0f / (float)T;
        const float invTK = 1.0f / ((float)T * 2.0f);
        #pragma unroll
        for (int e = 0; e < E; e++) {
            const float cnt  = atomicAdd(&g_acc[e], 0.0f);
            const float psum = atomicAdd(&g_acc[E + e], 0.0f);
            aux += (psum * invT) * (cnt * invTK * (float)E);
        }
        out_aux[0] = aux * ALPHA;
        #pragma unroll
        for (int i = 0; i < 2 * E; i++) {
            float old = atomicAdd(&g_acc[i], 0.0f);
            atomicAdd(&g_acc[i], -old);
        }
        atomicExch(&g_done, 0u);
    }
}

extern "C" void kernel_launch(void* const* d_in, const int* in_sizes, int n_in,
                              void* d_out, int out_size)
{
    const float* x = (const float*)d_in[0];   // [T, H]
    const float* w = (const float*)d_in[1];   // [E, H]
    const int T = in_sizes[0] / H;            // 16384

    float* out = (float*)d_out;
    float* out_idx = out;
    float* out_wgt = out + (size_t)T * 2;
    float* out_aux = out + (size_t)T * 4;

    const int smem_bytes = W_BYTES + NBUF * XBUF_BYTES;   // 204800
    cudaFuncSetAttribute(moe_gate_kernel,
                         cudaFuncAttributeMaxDynamicSharedMemorySize, smem_bytes);

    moe_gate_kernel<<<T / TPB, NTHR, smem_bytes>>>(x, w, out_idx, out_wgt, out_aux, T);
}

// round 7
// speedup vs baseline: 1.4958x; 1.4958x over previous
#include <cuda_runtime.h>
#include <math.h>

#define H       2048
#define E       8
#define TPW     4               // tokens per warp
#define NWARPS  8
#define TPB     (TPW * NWARPS)  // 32 tokens per block
#define NTHR    256
#define NIT     16              // stages; each covers 128 floats of H per token
#define DEPTH   3               // ring depth (prefetch distance 2)
#define STG_B   (TPW * 512)     // 2048 B per warp-stage (4 tok x 32 lanes x 16B)
#define RING_B  (DEPTH * STG_B) // 6144 B per warp
#define W_BYTES (E * H * 4)     // 65536
#define ALPHA   0.01f

__device__ float        g_acc[2 * E];   // [0..7] counts, [8..15] prob sums
__device__ unsigned int g_done = 0;

__device__ __forceinline__ void cp16(unsigned int saddr, const void* gaddr)
{
    asm volatile("cp.async.cg.shared.global [%0], [%1], 16;"
                 :: "r"(saddr), "l"(gaddr));
}

__global__ __launch_bounds__(NTHR, 2)
void moe_gate_kernel(const float* __restrict__ x,
                     const float* __restrict__ w,
                     float* __restrict__ out_idx,
                     float* __restrict__ out_wgt,
                     float* __restrict__ out_aux,
                     int T)
{
    extern __shared__ char smem[];
    float* wsm  = reinterpret_cast<float*>(smem);     // 64KB weights
    char*  ring = smem + W_BYTES;                     // 8 warps x 6KB rings

    __shared__ float s_cnt[E];
    __shared__ float s_psum[E];
    __shared__ unsigned int s_last;

    const int tid  = threadIdx.x;
    const int warp = tid >> 5;
    const int lane = tid & 31;
    const int tok0 = blockIdx.x * TPB + warp * TPW;

    if (tid < E)            s_cnt[tid] = 0.0f;
    else if (tid < 2 * E)   s_psum[tid - E] = 0.0f;

    const unsigned int ring_u32 =
        (unsigned int)__cvta_generic_to_shared(ring) + warp * RING_B
        + lane * 16;
    const char* ring_gen = ring + warp * RING_B + lane * 16;
    const float* xg = x + (size_t)tok0 * H + lane * 4;

    // issue one stage (128 floats of H for each of 4 tokens) into ring buf
    auto issue_stage = [&](int s, int buf) {
        const unsigned int sb = ring_u32 + buf * STG_B;
        const float*       g  = xg + s * 128;
        #pragma unroll
        for (int t = 0; t < TPW; t++)
            cp16(sb + t * 512, g + (size_t)t * H);
        asm volatile("cp.async.commit_group;");
    };

    // prologue: stages 0,1 in flight, then stage weights (once per block)
    issue_stage(0, 0);
    issue_stage(1, 1);
    {
        float4*       ws = reinterpret_cast<float4*>(wsm);
        const float4* wg = reinterpret_cast<const float4*>(w);
        #pragma unroll
        for (int i = 0; i < (E * H / 4) / NTHR; i++)
            ws[tid + i * NTHR] = wg[tid + i * NTHR];
    }
    __syncthreads();

    float acc[TPW][E];
    #pragma unroll
    for (int t = 0; t < TPW; t++)
        #pragma unroll
        for (int e = 0; e < E; e++)
            acc[t][e] = 0.0f;

    const float* wl = wsm + lane * 4;
    int buf_w = 2, buf_r = 0;

    for (int it = 0; it < NIT; it++) {
        if (it + 2 < NIT) {
            issue_stage(it + 2, buf_w);
            if (++buf_w == DEPTH) buf_w = 0;
        } else {
            asm volatile("cp.async.commit_group;");   // keep group count uniform
        }
        asm volatile("cp.async.wait_group 2;");       // stage 'it' complete

        const char* xp = ring_gen + buf_r * STG_B;
        if (++buf_r == DEPTH) buf_r = 0;

        float4 xv[TPW];
        #pragma unroll
        for (int t = 0; t < TPW; t++)
            xv[t] = *reinterpret_cast<const float4*>(xp + t * 512);

        const float* wst = wl + it * 128;
        #pragma unroll
        for (int e = 0; e < E; e++) {
            const float4 wv = *reinterpret_cast<const float4*>(wst + (size_t)e * H);
            #pragma unroll
            for (int t = 0; t < TPW; t++) {
                acc[t][e] = fmaf(xv[t].x, wv.x, acc[t][e]);
                acc[t][e] = fmaf(xv[t].y, wv.y, acc[t][e]);
                acc[t][e] = fmaf(xv[t].z, wv.z, acc[t][e]);
                acc[t][e] = fmaf(xv[t].w, wv.w, acc[t][e]);
            }
        }
    }

    // warp tree-reduce (all lanes end with full sums)
    #pragma unroll
    for (int t = 0; t < TPW; t++)
        #pragma unroll
        for (int e = 0; e < E; e++) {
            float v = acc[t][e];
            v += __shfl_xor_sync(0xffffffffu, v, 16);
            v += __shfl_xor_sync(0xffffffffu, v, 8);
            v += __shfl_xor_sync(0xffffffffu, v, 4);
            v += __shfl_xor_sync(0xffffffffu, v, 2);
            v += __shfl_xor_sync(0xffffffffu, v, 1);
            acc[t][e] = v;
        }

    if (lane < TPW) {
        const int tok = tok0 + lane;
        float lg[E];
        #pragma unroll
        for (int e = 0; e < E; e++) lg[e] = acc[lane][e];

        float m = lg[0];
        #pragma unroll
        for (int e = 1; e < E; e++) m = fmaxf(m, lg[e]);
        float p[E];
        float s = 0.0f;
        #pragma unroll
        for (int e = 0; e < E; e++) { p[e] = __expf(lg[e] - m); s += p[e]; }
        const float inv = 1.0f / s;

        int i1 = 0; float b1 = lg[0];
        #pragma unroll
        for (int e = 1; e < E; e++)
            if (lg[e] > b1) { b1 = lg[e]; i1 = e; }
        int i2 = -1; float b2 = -INFINITY;
        #pragma unroll
        for (int e = 0; e < E; e++)
            if (e != i1 && lg[e] > b2) { b2 = lg[e]; i2 = e; }

        out_idx[2 * tok]     = (float)i1;
        out_idx[2 * tok + 1] = (float)i2;
        out_wgt[2 * tok]     = p[i1] * inv;
        out_wgt[2 * tok + 1] = p[i2] * inv;

        atomicAdd(&s_cnt[i1], 1.0f);
        atomicAdd(&s_cnt[i2], 1.0f);
        #pragma unroll
        for (int e = 0; e < E; e++)
            atomicAdd(&s_psum[e], p[e] * inv);
    }

    __syncthreads();
    if (tid < E)           atomicAdd(&g_acc[tid], s_cnt[tid]);
    else if (tid < 2 * E)  atomicAdd(&g_acc[tid], s_psum[tid - E]);
    __threadfence();
    __syncthreads();

    // fused finalize: last block computes aux_loss and resets accumulators
    if (tid == 0)
        s_last = (atomicAdd(&g_done, 1u) == gridDim.x - 1) ? 1u : 0u;
    __syncthreads();

    if (s_last && tid == 0) {
        float aux = 0.0f;
        const float invT  = 1.0f / (float)T;
        const float invTK = 1.0f / ((float)T * 2.0f);
        #pragma unroll
        for (int e = 0; e < E; e++) {
            const float cnt  = atomicAdd(&g_acc[e], 0.0f);
            const float psum = atomicAdd(&g_acc[E + e], 0.0f);
            aux += (psum * invT) * (cnt * invTK * (float)E);
        }
        out_aux[0] = aux * ALPHA;
        #pragma unroll
        for (int i = 0; i < 2 * E; i++) {
            float old = atomicAdd(&g_acc[i], 0.0f);
            atomicAdd(&g_acc[i], -old);
        }
        atomicExch(&g_done, 0u);
    }
}

extern "C" void kernel_launch(void* const* d_in, const int* in_sizes, int n_in,
                              void* d_out, int out_size)
{
    const float* x = (const float*)d_in[0];   // [T, H]
    const float* w = (const float*)d_in[1];   // [E, H]
    const int T = in_sizes[0] / H;            // 16384

    float* out = (float*)d_out;
    float* out_idx = out;
    float* out_wgt = out + (size_t)T * 2;
    float* out_aux = out + (size_t)T * 4;

    const int smem_bytes = W_BYTES + NWARPS * RING_B;   // 64KB + 48KB = 112KB
    cudaFuncSetAttribute(moe_gate_kernel,
                         cudaFuncAttributeMaxDynamicSharedMemorySize, smem_bytes);

    moe_gate_kernel<<<T / TPB, NTHR, smem_bytes>>>(x, w, out_idx, out_wgt, out_aux, T);
}

// round 8
// speedup vs baseline: 1.5134x; 1.0118x over previous
#include <cuda_runtime.h>
#include <math.h>

#define H       2048
#define E       8
#define TPW     4               // tokens per warp
#define NWARPS  8
#define TPB     (TPW * NWARPS)  // 32 tokens per block
#define NTHR    256
#define NIT     16              // stages; each covers 128 floats of H per token
#define DEPTH   4               // ring depth
#define PF      3               // prefetch distance (stages ahead)
#define STG_B   (TPW * 512)     // 2048 B per warp-stage
#define RING_B  (DEPTH * STG_B) // 8192 B per warp
#define ALPHA   0.01f

__device__ float        g_acc[2 * E];   // [0..7] counts, [8..15] prob sums
__device__ unsigned int g_done = 0;

__device__ __forceinline__ void ffma2(unsigned long long& d,
                                      unsigned long long a,
                                      unsigned long long b)
{
    asm("fma.rn.f32x2 %0, %1, %2, %0;" : "+l"(d) : "l"(a), "l"(b));
}

__device__ __forceinline__ float pair_sum(unsigned long long p)
{
    float lo, hi;
    asm("mov.b64 {%0, %1}, %2;" : "=f"(lo), "=f"(hi) : "l"(p));
    return lo + hi;
}

__device__ __forceinline__ void cp16(unsigned int saddr, const void* gaddr)
{
    asm volatile("cp.async.cg.shared.global [%0], [%1], 16;"
                 :: "r"(saddr), "l"(gaddr));
}

__global__ __launch_bounds__(NTHR, 2)
void moe_gate_kernel(const float* __restrict__ x,
                     const float* __restrict__ w,
                     float* __restrict__ out_idx,
                     float* __restrict__ out_wgt,
                     float* __restrict__ out_aux,
                     int T)
{
    extern __shared__ char smem[];        // 8 warps x 8KB rings = 64KB
    __shared__ float s_cnt[E];
    __shared__ float s_psum[E];
    __shared__ unsigned int s_last;

    const int tid  = threadIdx.x;
    const int warp = tid >> 5;
    const int lane = tid & 31;
    const int tok0 = blockIdx.x * TPB + warp * TPW;

    const unsigned int ring_u32 =
        (unsigned int)__cvta_generic_to_shared(smem) + warp * RING_B + lane * 16;
    const char*  ring_gen = smem + warp * RING_B + lane * 16;
    const float* xg = x + (size_t)tok0 * H + lane * 4;

    auto issue_stage = [&](int s) {
        const unsigned int sb = ring_u32 + (s & (DEPTH - 1)) * STG_B;
        const float*       g  = xg + s * 128;
        #pragma unroll
        for (int t = 0; t < TPW; t++)
            cp16(sb + t * 512, g + (size_t)t * H);
        asm volatile("cp.async.commit_group;");
    };

    // prologue: PF stages in flight immediately (DRAM starts now)
    issue_stage(0);
    issue_stage(1);
    issue_stage(2);

    if (tid < E)            s_cnt[tid] = 0.0f;
    else if (tid < 2 * E)   s_psum[tid - E] = 0.0f;
    __syncthreads();        // s_cnt/s_psum visible before any epilogue atomics

    unsigned long long acc2[TPW][E];
    #pragma unroll
    for (int t = 0; t < TPW; t++)
        #pragma unroll
        for (int e = 0; e < E; e++)
            acc2[t][e] = 0ull;

    const float* wl = w + lane * 4;       // weights straight from L1

    for (int it = 0; it < NIT; it++) {
        if (it + PF < NIT) issue_stage(it + PF);
        else               asm volatile("cp.async.commit_group;");
        asm volatile("cp.async.wait_group 3;");   // stage 'it' complete

        const char* xp = ring_gen + (it & (DEPTH - 1)) * STG_B;
        ulonglong2 xv[TPW];
        #pragma unroll
        for (int t = 0; t < TPW; t++)
            xv[t] = *reinterpret_cast<const ulonglong2*>(xp + t * 512);

        const float* wst = wl + it * 128;
        #pragma unroll
        for (int e = 0; e < E; e++) {
            const ulonglong2 wv =
                *reinterpret_cast<const ulonglong2*>(wst + (size_t)e * H);
            #pragma unroll
            for (int t = 0; t < TPW; t++) {
                ffma2(acc2[t][e], xv[t].x, wv.x);
                ffma2(acc2[t][e], xv[t].y, wv.y);
            }
        }
    }

    // unpack + warp tree-reduce
    float accf[TPW][E];
    #pragma unroll
    for (int t = 0; t < TPW; t++)
        #pragma unroll
        for (int e = 0; e < E; e++) {
            float v = pair_sum(acc2[t][e]);
            v += __shfl_xor_sync(0xffffffffu, v, 16);
            v += __shfl_xor_sync(0xffffffffu, v, 8);
            v += __shfl_xor_sync(0xffffffffu, v, 4);
            v += __shfl_xor_sync(0xffffffffu, v, 2);
            v += __shfl_xor_sync(0xffffffffu, v, 1);
            accf[t][e] = v;
        }

    if (lane < TPW) {
        const int tok = tok0 + lane;
        float lg[E];
        #pragma unroll
        for (int e = 0; e < E; e++) lg[e] = accf[lane][e];

        float m = lg[0];
        #pragma unroll
        for (int e = 1; e < E; e++) m = fmaxf(m, lg[e]);
        float p[E];
        float s = 0.0f;
        #pragma unroll
        for (int e = 0; e < E; e++) { p[e] = __expf(lg[e] - m); s += p[e]; }
        const float inv = 1.0f / s;

        int i1 = 0; float b1 = lg[0];
        #pragma unroll
        for (int e = 1; e < E; e++)
            if (lg[e] > b1) { b1 = lg[e]; i1 = e; }
        int i2 = -1; float b2 = -INFINITY;
        #pragma unroll
        for (int e = 0; e < E; e++)
            if (e != i1 && lg[e] > b2) { b2 = lg[e]; i2 = e; }

        out_idx[2 * tok]     = (float)i1;
        out_idx[2 * tok + 1] = (float)i2;
        out_wgt[2 * tok]     = p[i1] * inv;
        out_wgt[2 * tok + 1] = p[i2] * inv;

        atomicAdd(&s_cnt[i1], 1.0f);
        atomicAdd(&s_cnt[i2], 1.0f);
        #pragma unroll
        for (int e = 0; e < E; e++)
            atomicAdd(&s_psum[e], p[e] * inv);
    }

    __syncthreads();
    if (tid < E)           atomicAdd(&g_acc[tid], s_cnt[tid]);
    else if (tid < 2 * E)  atomicAdd(&g_acc[tid], s_psum[tid - E]);
    __threadfence();
    __syncthreads();

    // fused finalize: last block computes aux_loss and resets accumulators
    if (tid == 0)
        s_last = (atomicAdd(&g_done, 1u) == gridDim.x - 1) ? 1u : 0u;
    __syncthreads();

    if (s_last && tid == 0) {
        float aux = 0.0f;
        const float invT  = 1.0f / (float)T;
        const float invTK = 1.0f / ((float)T * 2.0f);
        #pragma unroll
        for (int e = 0; e < E; e++) {
            const float cnt  = atomicAdd(&g_acc[e], 0.0f);
            const float psum = atomicAdd(&g_acc[E + e], 0.0f);
            aux += (psum * invT) * (cnt * invTK * (float)E);
        }
        out_aux[0] = aux * ALPHA;
        #pragma unroll
        for (int i = 0; i < 2 * E; i++) {
            float old = atomicAdd(&g_acc[i], 0.0f);
            atomicAdd(&g_acc[i], -old);
        }
        atomicExch(&g_done, 0u);
    }
}

extern "C" void kernel_launch(void* const* d_in, const int* in_sizes, int n_in,
                              void* d_out, int out_size)
{
    const float* x = (const float*)d_in[0];   // [T, H]
    const float* w = (const float*)d_in[1];   // [E, H]
    const int T = in_sizes[0] / H;            // 16384

    float* out = (float*)d_out;
    float* out_idx = out;
    float* out_wgt = out + (size_t)T * 2;
    float* out_aux = out + (size_t)T * 4;

    const int smem_bytes = NWARPS * RING_B;   // 64KB rings only
    cudaFuncSetAttribute(moe_gate_kernel,
                         cudaFuncAttributeMaxDynamicSharedMemorySize, smem_bytes);

    moe_gate_kernel<<<T / TPB, NTHR, smem_bytes>>>(x, w, out_idx, out_wgt, out_aux, T);
}